// round 8
// baseline (speedup 1.0000x reference)
#include <cuda_runtime.h>
#include <cuda_bf16.h>
#include <cstdint>
#include <math.h>

#define N 8192
#define D 128
#define NCTA 148
#define NTT 2080               /* upper-triangle tiles: 64*65/2 */
#define NTHR 512
#define INV_T 14.2857142857142857f
#define LN2 0.69314718055994531f
#define SQRT_C 4.5398160486f   /* sqrt((1/0.07)*log2(e)) */
#define THRESH 0.1f

// Scratch (no cudaMalloc allowed)
__device__ __nv_bfloat16 g_fbf[N * D];       // normalized * SQRT_C, bf16
__device__ float g_fn[N * D];                // normalized, fp32
__device__ float g_pref[(N + 1) * D];        // exclusive prefix sums (sorted order)
__device__ float g_csum[32 * D];             // per-chunk sums
__device__ float g_slab[N];                  // sorted labels
__device__ int   g_sidx[N];                  // sorted -> original index
__device__ float g_den[N];
__device__ float g_loss;
__device__ unsigned int g_done;

// ---- main kernel SMEM layout (bytes) ----
#define SM_RES   0          /* resident 128-row j-strip, 32 KB, XOR-swizzled */
#define SM_STR   32768      /* 2 x 32 KB double-buffered streaming A tiles */
#define SM_TOTAL 98304

__device__ __forceinline__ uint32_t smem_u32(const void* p) {
    uint32_t a;
    asm("{ .reg .u64 t; cvta.to.shared.u64 t, %1; cvt.u32.u64 %0, t; }" : "=r"(a) : "l"(p));
    return a;
}
__device__ __forceinline__ float ex2(float x) {
    float r;
    asm("ex2.approx.ftz.f32 %0, %1;" : "=f"(r) : "f"(x));
    return r;
}

#define LDSM_X4(r0, r1, r2, r3, addr) \
    asm volatile("ldmatrix.sync.aligned.m8n8.x4.shared.b16 {%0,%1,%2,%3}, [%4];" \
                 : "=r"(r0), "=r"(r1), "=r"(r2), "=r"(r3) : "r"(addr))

#define MMA16816(d, a, b) \
    asm volatile("mma.sync.aligned.m16n8k16.row.col.f32.bf16.bf16.f32 " \
                 "{%0,%1,%2,%3}, {%4,%5,%6,%7}, {%8,%9}, {%0,%1,%2,%3};" \
                 : "+f"((d)[0]), "+f"((d)[1]), "+f"((d)[2]), "+f"((d)[3]) \
                 : "r"((a)[0]), "r"((a)[1]), "r"((a)[2]), "r"((a)[3]), \
                   "r"((b)[0]), "r"((b)[1]))

#define CP_ASYNC16(dst, src) \
    asm volatile("cp.async.cg.shared.global [%0], [%1], 16;" \
                 :: "r"(dst), "l"(src) : "memory")
#define CP_COMMIT() asm volatile("cp.async.commit_group;" ::: "memory")
#define CP_WAIT0()  asm volatile("cp.async.wait_group 0;" ::: "memory")

__device__ __forceinline__ uint32_t swz(int row, int seg) {
    return (uint32_t)(row * 256 + ((seg ^ (row & 7)) << 4));
}

__device__ __forceinline__ void cp_tile(uint32_t dst_base, int rowBase, int tid) {
    size_t gsrc = __cvta_generic_to_global(g_fbf) + (size_t)rowBase * 256;
    #pragma unroll
    for (int it = 0; it < 4; it++) {
        int u = it * NTHR + tid;         // 2048 16B units
        int row = u >> 4, seg = u & 15;
        CP_ASYNC16(dst_base + swz(row, seg), (const void*)(gsrc + (size_t)u * 16));
    }
}

// ---------------------------------------------------------------------------
// Kernel 1: normalize rows (clamp at 1e-8); store fp32 copy and bf16*SQRT_C
// copy; zero accumulators.
// ---------------------------------------------------------------------------
__global__ void prep_kernel(const float* __restrict__ features) {
    int warp = threadIdx.x >> 5, lane = threadIdx.x & 31;
    int row = blockIdx.x * 8 + warp;

    float4 v = ((const float4*)(features + row * D))[lane];
    float ss = v.x * v.x + v.y * v.y + v.z * v.z + v.w * v.w;
    #pragma unroll
    for (int off = 16; off; off >>= 1) ss += __shfl_xor_sync(0xffffffffu, ss, off);
    float sc = 1.0f / fmaxf(sqrtf(ss), 1e-8f);

    float4 nv;
    nv.x = v.x * sc; nv.y = v.y * sc; nv.z = v.z * sc; nv.w = v.w * sc;
    ((float4*)(g_fn + (size_t)row * D))[lane] = nv;

    __nv_bfloat162 p0 = __floats2bfloat162_rn(nv.x * SQRT_C, nv.y * SQRT_C);
    __nv_bfloat162 p1 = __floats2bfloat162_rn(nv.z * SQRT_C, nv.w * SQRT_C);
    uint2 st;
    st.x = *(const uint32_t*)&p0;
    st.y = *(const uint32_t*)&p1;
    ((uint2*)(g_fbf + (size_t)row * D))[lane] = st;

    int gt = blockIdx.x * blockDim.x + threadIdx.x;
    if (gt < N) g_den[gt] = 0.0f;
    if (gt == 0) { g_done = 0; g_loss = 0.0f; }
}

// ---------------------------------------------------------------------------
// Kernel 2: bitonic sort of (label,idx) pairs. One CTA, 1024 threads, 64KB smem.
// ---------------------------------------------------------------------------
__global__ void sort_kernel(const float* __restrict__ labels) {
    extern __shared__ unsigned long long skeys[];
    const int tid = threadIdx.x;

    for (int k = tid; k < N; k += 1024)
        skeys[k] = ((unsigned long long)__float_as_uint(labels[k]) << 32) | (unsigned)k;

    for (int size = 2; size <= N; size <<= 1) {
        for (int stride = size >> 1; stride > 0; stride >>= 1) {
            __syncthreads();
            #pragma unroll 1
            for (int i = tid; i < N; i += 1024) {
                int j = i ^ stride;
                if (j > i) {
                    unsigned long long a = skeys[i], b = skeys[j];
                    bool asc = ((i & size) == 0);
                    if ((a > b) == asc) { skeys[i] = b; skeys[j] = a; }
                }
            }
        }
    }
    __syncthreads();
    for (int k = tid; k < N; k += 1024) {
        unsigned long long v = skeys[k];
        g_slab[k] = __uint_as_float((uint32_t)(v >> 32));
        g_sidx[k] = (int)(v & 0xffffffffu);
    }
}

// ---------------------------------------------------------------------------
// Kernel 3a: per-chunk feature sums in sorted order (32 chunks of 256)
// ---------------------------------------------------------------------------
__global__ void scan1_kernel() {
    const int d = threadIdx.x;          // 128 threads
    const int base = blockIdx.x * 256;
    float s0 = 0.0f, s1 = 0.0f;
    for (int kk = 0; kk < 256; kk += 2) {
        s0 += g_fn[(size_t)g_sidx[base + kk] * D + d];
        s1 += g_fn[(size_t)g_sidx[base + kk + 1] * D + d];
    }
    g_csum[blockIdx.x * D + d] = s0 + s1;
}

// ---------------------------------------------------------------------------
// Kernel 3b: write exclusive prefix sums P[k][d] (k = 0..N; sorted order)
// ---------------------------------------------------------------------------
__global__ void scan2_kernel() {
    const int d = threadIdx.x;          // 128 threads
    const int c = blockIdx.x;
    float off = 0.0f;
    for (int cc = 0; cc < c; cc++) off += g_csum[cc * D + d];
    float run = off;
    const int base = c * 256;
    for (int kk = 0; kk < 256; kk++) {
        int k = base + kk;
        g_pref[(size_t)k * D + d] = run;
        run += g_fn[(size_t)g_sidx[k] * D + d];
    }
    if (c == 31) g_pref[(size_t)N * D + d] = run;
}

// ---------------------------------------------------------------------------
// Kernel 4: persistent fused HMMA GEMM over the upper triangle, column-major
// strip walk. Epilogue = denominator only (exp-sum, dual row/col update).
// ---------------------------------------------------------------------------
__global__ void __launch_bounds__(NTHR, 1)
main_kernel() {
    extern __shared__ char smem[];
    const uint32_t sb = smem_u32(smem);
    const int tid  = threadIdx.x;
    const int wid  = tid >> 5;
    const int lane = tid & 31;
    const int wm = wid & 3;          // 0..3 -> m-block of 32
    const int wn = wid >> 2;         // 0..3 -> n-block of 32
    const int quad = lane >> 2;
    const int qt   = lane & 3;

    // --- ldmatrix per-lane bases ---
    const int rowA = wm * 32 + (lane & 15);
    const int hiA  = lane >> 4;
    const int r7A  = rowA & 7;
    const uint32_t aRowOff = (uint32_t)(rowA * 256);
    const int g   = lane >> 3;
    const int r8  = lane & 7;
    const int nrowb = wn * 32 + ((g >> 1) << 3) + r8;
    const int segbLo = g & 1;
    const uint32_t bBase = sb + SM_RES + (uint32_t)(nrowb * 256);

    const int t0 = ((int)blockIdx.x * NTT) / NCTA;
    const int t1 = (((int)blockIdx.x + 1) * NTT) / NCTA;

    // map t0 -> (tj, ti): column-major triangle, strip tj has tj+1 tiles
    int tj = 0, rem = t0;
    while (rem >= tj + 1) { rem -= tj + 1; tj++; }
    int ti = rem;

    cp_tile(sb + SM_RES, tj * 128, tid);
    cp_tile(sb + SM_STR + (t0 & 1) * 32768, ti * 128, tid);
    CP_COMMIT();
    CP_WAIT0();
    __syncthreads();

    float cdn[8];
    #pragma unroll
    for (int p = 0; p < 8; p++) cdn[p] = 0.0f;

    for (int t = t0; t < t1; t++) {
        const int s = t & 1;
        const bool have_next = (t + 1) < t1;

        int nti = ti + 1, ntj = tj;
        if (nti > tj) { ntj = tj + 1; nti = 0; }
        const bool strip_change = have_next && (ntj != tj);

        if (have_next) {
            cp_tile(sb + SM_STR + ((t + 1) & 1) * 32768, nti * 128, tid);
            CP_COMMIT();
        }

        // ---- mainloop: 128x128 tile, K=128 ----
        float acc[2][4][4];
        #pragma unroll
        for (int mi = 0; mi < 2; mi++)
            #pragma unroll
            for (int ni = 0; ni < 4; ni++)
                #pragma unroll
                for (int r = 0; r < 4; r++) acc[mi][ni][r] = 0.0f;

        const uint32_t aBase = sb + SM_STR + s * 32768 + aRowOff;
        #pragma unroll
        for (int k = 0; k < 8; k++) {
            uint32_t a[2][4];
            #pragma unroll
            for (int mi = 0; mi < 2; mi++) {
                uint32_t addr = aBase + mi * 4096 + ((((k * 2 + hiA) ^ r7A)) << 4);
                LDSM_X4(a[mi][0], a[mi][1], a[mi][2], a[mi][3], addr);
            }
            uint32_t b[4][2];
            #pragma unroll
            for (int p = 0; p < 2; p++) {
                uint32_t addr = bBase + p * 4096 + ((((k * 2 + segbLo) ^ r8)) << 4);
                LDSM_X4(b[2 * p][0], b[2 * p][1], b[2 * p + 1][0], b[2 * p + 1][1], addr);
            }
            #pragma unroll
            for (int mi = 0; mi < 2; mi++)
                #pragma unroll
                for (int ni = 0; ni < 4; ni++)
                    MMA16816(acc[mi][ni], a[mi], b[ni]);
        }

        // ---- epilogue: denominator only. acc is already the ex2 argument.
        float dn[4] = {0.0f, 0.0f, 0.0f, 0.0f};
        if (ti == tj) {
            // diagonal: full tile, row-only, self-excluded
            #pragma unroll
            for (int mi = 0; mi < 2; mi++) {
                #pragma unroll
                for (int rh = 0; rh < 2; rh++) {
                    const int slot = mi * 2 + rh;
                    const int selfnl = wm * 32 + mi * 16 + quad + rh * 8;
                    #pragma unroll
                    for (int p = 0; p < 8; p++) {
                        const int ni = p >> 1, c = p & 1;
                        const int nl = wn * 32 + ni * 8 + qt * 2 + c;
                        float e = ex2(acc[mi][ni][rh * 2 + c]);
                        dn[slot] += (nl == selfnl) ? 0.0f : e;
                    }
                }
            }
        } else {
            // off-diagonal: dual row + column update
            #pragma unroll
            for (int p = 0; p < 8; p++) {
                const int ni = p >> 1, c = p & 1;
                float a0 = 0.0f;
                #pragma unroll
                for (int mi = 0; mi < 2; mi++) {
                    #pragma unroll
                    for (int rh = 0; rh < 2; rh++) {
                        float e = ex2(acc[mi][ni][rh * 2 + c]);
                        dn[mi * 2 + rh] += e;
                        a0 += e;
                    }
                }
                cdn[p] += a0;
            }
        }

        // ---- row flush: every tile (2-round qt shuffle) ----
        #pragma unroll
        for (int s2 = 0; s2 < 4; s2++) {
            float a = dn[s2];
            a += __shfl_xor_sync(0xffffffffu, a, 1);
            a += __shfl_xor_sync(0xffffffffu, a, 2);
            if (qt == 0) {
                int gim = ti * 128 + wm * 32 + (s2 >> 1) * 16 + quad + (s2 & 1) * 8;
                atomicAdd(&g_den[gim], a);
            }
        }

        // ---- column flush at strip end / range end ----
        if (strip_change || !have_next) {
            #pragma unroll
            for (int p = 0; p < 8; p++) {
                float a = cdn[p];
                #pragma unroll
                for (int off = 4; off <= 16; off <<= 1)
                    a += __shfl_xor_sync(0xffffffffu, a, off);
                if (quad == 0) {
                    int gj = tj * 128 + wn * 32 + (p >> 1) * 8 + qt * 2 + (p & 1);
                    atomicAdd(&g_den[gj], a);
                }
                cdn[p] = 0.0f;
            }
        }

        CP_WAIT0();
        __syncthreads();

        if (strip_change) {
            cp_tile(sb + SM_RES, ntj * 128, tid);
            CP_COMMIT();
            CP_WAIT0();
            __syncthreads();
        }
        ti = nti; tj = ntj;
    }
}

// ---------------------------------------------------------------------------
// Kernel 5: per-row positive stats via sorted windows + prefix sums, then
// loss accumulation; last block writes the final scalar.
// One warp per sorted position.
// ---------------------------------------------------------------------------
__global__ void final_kernel(float* __restrict__ out) {
    const int tid = threadIdx.x;
    const int wid = tid >> 5;
    const int lane = tid & 31;
    const int gw = blockIdx.x * 8 + wid;   // 64 blocks x 8 warps = 512 warps

    float wsum = 0.0f;   // lane0-held partial loss over this warp's k's

    #pragma unroll 1
    for (int it = 0; it < 16; it++) {
        const int k = gw + 512 * it;
        const float li = g_slab[k];
        const int i = g_sidx[k];

        // window [lo, hi): |li - slab[m]| < 0.1 (exact fp32 one-sided forms)
        int l = 0, r = N;
        while (l < r) { int m = (l + r) >> 1; if (li - g_slab[m] < THRESH) r = m; else l = m + 1; }
        const int lo = l;
        l = 0; r = N;
        while (l < r) { int m = (l + r) >> 1; if (g_slab[m] - li < THRESH) l = m + 1; else r = m; }
        const int hi = l;

        // dot = f_i . (P[hi] - P[lo]) over 128 dims (4 per lane)
        float dot = 0.0f;
        const float* fi = g_fn + (size_t)i * D;
        const float* Ph = g_pref + (size_t)hi * D;
        const float* Pl = g_pref + (size_t)lo * D;
        #pragma unroll
        for (int q = 0; q < 4; q++) {
            int d = lane + q * 32;
            dot += fi[d] * (Ph[d] - Pl[d]);
        }
        #pragma unroll
        for (int off = 16; off; off >>= 1)
            dot += __shfl_xor_sync(0xffffffffu, dot, off);

        if (lane == 0) {
            float pcv = (float)(hi - lo - 1);
            float term = (dot - 1.0f) * INV_T / pcv - LN2 * log2f(g_den[i]);
            wsum += term;
        }
    }

    if (lane == 0) atomicAdd(&g_loss, wsum);

    __threadfence();
    __syncthreads();
    __shared__ unsigned int s_ticket;
    if (tid == 0) s_ticket = atomicAdd(&g_done, 1u);
    __syncthreads();
    if (s_ticket == gridDim.x - 1 && tid == 0) {
        float total = atomicAdd(&g_loss, 0.0f);
        out[0] = -total / (float)N;
    }
}

// ---------------------------------------------------------------------------
extern "C" void kernel_launch(void* const* d_in, const int* in_sizes, int n_in,
                              void* d_out, int out_size) {
    const float* features = (const float*)d_in[0];
    const float* labels   = (const float*)d_in[1];
    float* out = (float*)d_out;

    cudaFuncSetAttribute(main_kernel, cudaFuncAttributeMaxDynamicSharedMemorySize, SM_TOTAL);
    cudaFuncSetAttribute(sort_kernel, cudaFuncAttributeMaxDynamicSharedMemorySize, 65536);

    prep_kernel<<<N / 8, 256>>>(features);
    sort_kernel<<<1, 1024, 65536>>>(labels);
    scan1_kernel<<<32, 128>>>();
    scan2_kernel<<<32, 128>>>();
    main_kernel<<<NCTA, NTHR, SM_TOTAL>>>();
    final_kernel<<<64, 256>>>(out);
}

// round 9
// speedup vs baseline: 1.8116x; 1.8116x over previous
#include <cuda_runtime.h>
#include <cuda_bf16.h>
#include <cstdint>
#include <math.h>

#define N 8192
#define D 128
#define NCTA 148
#define NTT 2080               /* upper-triangle tiles: 64*65/2 */
#define NTHR 512
#define NBUCK 4096
#define INV_T 14.2857142857142857f
#define LN2 0.69314718055994531f
#define SQRT_C 4.5398160486f   /* sqrt((1/0.07)*log2(e)) */
#define THRESH 0.1f

// Scratch (no cudaMalloc allowed)
__device__ __nv_bfloat16 g_fbf[N * D];       // normalized * SQRT_C, bf16
__device__ float g_fn[N * D];                // normalized, fp32
__device__ float g_fp[N * D];                // normalized, sorted order
__device__ float g_pref[(N + 1) * D];        // exclusive prefix sums (sorted)
__device__ float g_csum[64 * D];             // per-chunk sums
__device__ float g_slab[N];                  // sorted labels
__device__ int   g_sidx[N];                  // sorted -> original index
__device__ float g_den[N];
__device__ float g_loss;
__device__ unsigned g_flag_sort, g_cnt_scan1, g_cnt_gemm, g_cnt_out;

// ---- main kernel SMEM layout (bytes) ----
#define SM_RES   0          /* resident 128-row j-strip, 32 KB, XOR-swizzled */
#define SM_STR   32768      /* 2 x 32 KB double-buffered streaming A tiles */
#define SM_TOTAL 98304      /* sort reuses all of it as scratch */

__device__ __forceinline__ uint32_t smem_u32(const void* p) {
    uint32_t a;
    asm("{ .reg .u64 t; cvta.to.shared.u64 t, %1; cvt.u32.u64 %0, t; }" : "=r"(a) : "l"(p));
    return a;
}
__device__ __forceinline__ float ex2(float x) {
    float r;
    asm("ex2.approx.ftz.f32 %0, %1;" : "=f"(r) : "f"(x));
    return r;
}
__device__ __forceinline__ unsigned ld_acq(unsigned* p) {
    unsigned v;
    asm volatile("ld.acquire.gpu.u32 %0, [%1];" : "=r"(v) : "l"(p) : "memory");
    return v;
}

#define LDSM_X4(r0, r1, r2, r3, addr) \
    asm volatile("ldmatrix.sync.aligned.m8n8.x4.shared.b16 {%0,%1,%2,%3}, [%4];" \
                 : "=r"(r0), "=r"(r1), "=r"(r2), "=r"(r3) : "r"(addr))

#define MMA16816(d, a, b) \
    asm volatile("mma.sync.aligned.m16n8k16.row.col.f32.bf16.bf16.f32 " \
                 "{%0,%1,%2,%3}, {%4,%5,%6,%7}, {%8,%9}, {%0,%1,%2,%3};" \
                 : "+f"((d)[0]), "+f"((d)[1]), "+f"((d)[2]), "+f"((d)[3]) \
                 : "r"((a)[0]), "r"((a)[1]), "r"((a)[2]), "r"((a)[3]), \
                   "r"((b)[0]), "r"((b)[1]))

#define CP_ASYNC16(dst, src) \
    asm volatile("cp.async.cg.shared.global [%0], [%1], 16;" \
                 :: "r"(dst), "l"(src) : "memory")
#define CP_COMMIT() asm volatile("cp.async.commit_group;" ::: "memory")
#define CP_WAIT0()  asm volatile("cp.async.wait_group 0;" ::: "memory")

__device__ __forceinline__ uint32_t swz(int row, int seg) {
    return (uint32_t)(row * 256 + ((seg ^ (row & 7)) << 4));
}

__device__ __forceinline__ void cp_tile(uint32_t dst_base, int rowBase, int tid) {
    size_t gsrc = __cvta_generic_to_global(g_fbf) + (size_t)rowBase * 256;
    #pragma unroll
    for (int it = 0; it < 4; it++) {
        int u = it * NTHR + tid;         // 2048 16B units
        int row = u >> 4, seg = u & 15;
        CP_ASYNC16(dst_base + swz(row, seg), (const void*)(gsrc + (size_t)u * 16));
    }
}

// weighted static tile split: CTA0 carries the sort, CTAs 1-8 the scans
__device__ __forceinline__ int cum_tiles(int i) {
    long long cw = (i >= 1 ? 50 : 0)
                 + 60LL * (i > 1 ? (i < 9 ? i - 1 : 8) : 0)
                 + 100LL * (i > 9 ? i - 9 : 0);
    const long long tot = 50 + 60 * 8 + 100 * 139;   // 14430
    return (int)((long long)NTT * cw / tot);
}

// ---------------------------------------------------------------------------
// Kernel 1: normalize rows (clamp at 1e-8); fp32 + bf16*SQRT_C copies; zero state
// ---------------------------------------------------------------------------
__global__ void prep_kernel(const float* __restrict__ features) {
    int warp = threadIdx.x >> 5, lane = threadIdx.x & 31;
    int row = blockIdx.x * 8 + warp;

    float4 v = ((const float4*)(features + row * D))[lane];
    float ss = v.x * v.x + v.y * v.y + v.z * v.z + v.w * v.w;
    #pragma unroll
    for (int off = 16; off; off >>= 1) ss += __shfl_xor_sync(0xffffffffu, ss, off);
    float sc = 1.0f / fmaxf(sqrtf(ss), 1e-8f);

    float4 nv;
    nv.x = v.x * sc; nv.y = v.y * sc; nv.z = v.z * sc; nv.w = v.w * sc;
    ((float4*)(g_fn + (size_t)row * D))[lane] = nv;

    __nv_bfloat162 p0 = __floats2bfloat162_rn(nv.x * SQRT_C, nv.y * SQRT_C);
    __nv_bfloat162 p1 = __floats2bfloat162_rn(nv.z * SQRT_C, nv.w * SQRT_C);
    uint2 st;
    st.x = *(const uint32_t*)&p0;
    st.y = *(const uint32_t*)&p1;
    ((uint2*)(g_fbf + (size_t)row * D))[lane] = st;

    int gt = blockIdx.x * blockDim.x + threadIdx.x;
    if (gt < N) g_den[gt] = 0.0f;
    if (gt == 0) {
        g_loss = 0.0f;
        g_flag_sort = 0u; g_cnt_scan1 = 0u; g_cnt_gemm = 0u; g_cnt_out = 0u;
    }
}

// ---------------------------------------------------------------------------
// Kernel 2: everything else, fused. Persistent 148 CTAs:
//   CTA 0: bucket-sort labels (smem scratch) -> flag
//   CTA 1-8: wait flag -> permute features to sorted order -> chunk sums ->
//            barrier(8) -> exclusive prefix sums
//   all:  weighted share of upper-triangle GEMM (denominator-only epilogue)
//   all:  grid barrier -> final loss (smem binary-search windows + prefix dots)
// ---------------------------------------------------------------------------
__global__ void __launch_bounds__(NTHR, 1)
main_kernel(const float* __restrict__ labels, float* __restrict__ out) {
    extern __shared__ char smem[];
    const uint32_t sb = smem_u32(smem);
    const int tid  = threadIdx.x;
    const int wid  = tid >> 5;
    const int lane = tid & 31;
    const int bid  = (int)blockIdx.x;

    __shared__ unsigned wtot[17];

    // ===================== phase L: label path =====================
    if (bid == 0) {
        // ---- bucket sort of (label, idx), exact total order ----
        unsigned long long* keys = (unsigned long long*)smem;       // 64 KB
        unsigned* cnt = (unsigned*)(smem + 65536);                  // 16 KB
        unsigned* bst = (unsigned*)(smem + 65536 + 16384);          // 16 KB

        for (int b = tid; b < NBUCK; b += NTHR) cnt[b] = 0u;
        __syncthreads();
        #pragma unroll 1
        for (int it = 0; it < 16; it++) {
            int k = it * NTHR + tid;
            float lv = labels[k];
            int b = (int)(lv * (float)NBUCK);
            b = max(0, min(NBUCK - 1, b));
            atomicAdd(&cnt[b], 1u);
        }
        __syncthreads();
        // exclusive scan of 4096 counts (8 per thread + warp scan + warp totals)
        unsigned loc[8]; unsigned s = 0u;
        #pragma unroll
        for (int j = 0; j < 8; j++) { loc[j] = s; s += cnt[tid * 8 + j]; }
        unsigned incl = s;
        #pragma unroll
        for (int off = 1; off < 32; off <<= 1) {
            unsigned v = __shfl_up_sync(0xffffffffu, incl, off);
            if (lane >= off) incl += v;
        }
        if (lane == 31) wtot[wid + 1] = incl;
        if (tid == 0) wtot[0] = 0u;
        __syncthreads();
        if (tid == 0)
            for (int w = 1; w <= 16; w++) wtot[w] += wtot[w - 1];
        __syncthreads();
        unsigned base = wtot[wid] + incl - s;
        #pragma unroll
        for (int j = 0; j < 8; j++) bst[tid * 8 + j] = base + loc[j];
        __syncthreads();
        // scatter (bst becomes bucket END after this)
        #pragma unroll 1
        for (int it = 0; it < 16; it++) {
            int k = it * NTHR + tid;
            float lv = labels[k];
            int b = max(0, min(NBUCK - 1, (int)(lv * (float)NBUCK)));
            unsigned pos = atomicAdd(&bst[b], 1u);
            keys[pos] = ((unsigned long long)__float_as_uint(lv) << 32) | (unsigned)k;
        }
        __syncthreads();
        // per-bucket insertion sort
        #pragma unroll 1
        for (int b = tid; b < NBUCK; b += NTHR) {
            unsigned st = (b == 0) ? 0u : bst[b - 1];
            unsigned n = cnt[b];
            for (unsigned x = st + 1; x < st + n; x++) {
                unsigned long long v = keys[x];
                unsigned y = x;
                while (y > st && keys[y - 1] > v) { keys[y] = keys[y - 1]; y--; }
                keys[y] = v;
            }
        }
        __syncthreads();
        for (int k = tid; k < N; k += NTHR) {
            unsigned long long v = keys[k];
            g_slab[k] = __uint_as_float((unsigned)(v >> 32));
            g_sidx[k] = (int)(v & 0xffffffffu);
        }
        __threadfence();
        __syncthreads();
        if (tid == 0) atomicExch(&g_flag_sort, 1u);
    } else if (bid <= 8) {
        // ---- permute + prefix-scan (needs sort) ----
        if (tid == 0) while (ld_acq(&g_flag_sort) == 0u) __nanosleep(64);
        __syncthreads();
        const int q = bid - 1;                 // 0..7
        {   // permute rows q*1024 .. +1023 into sorted order
            const int rb = q * 1024;
            #pragma unroll 1
            for (int it = 0; it < 64; it++) {
                int u = it * NTHR + tid;       // 32768 16B-units
                int row = rb + (u >> 5);
                int seg = u & 31;
                int src = g_sidx[row];
                ((float4*)(g_fp + (size_t)row * D))[seg] =
                    ((const float4*)(g_fn + (size_t)src * D))[seg];
            }
        }
        __syncthreads();
        {   // chunk sums: chunks 8q..8q+7, 4 thread-groups of 128
            const int grp = tid >> 7, d = tid & 127;
            #pragma unroll 1
            for (int cc = 0; cc < 2; cc++) {
                int c = q * 8 + cc * 4 + grp;
                const float* src = g_fp + (size_t)c * 128 * D + d;
                float s = 0.0f;
                #pragma unroll 8
                for (int r = 0; r < 128; r++) s += src[(size_t)r * D];
                g_csum[c * D + d] = s;
            }
        }
        __threadfence();
        __syncthreads();
        if (tid == 0) {
            atomicAdd(&g_cnt_scan1, 1u);
            while (ld_acq(&g_cnt_scan1) < 8u) __nanosleep(64);
        }
        __syncthreads();
        {   // exclusive prefix sums
            const int grp = tid >> 7, d = tid & 127;
            #pragma unroll 1
            for (int cc = 0; cc < 2; cc++) {
                int c = q * 8 + cc * 4 + grp;
                float off = 0.0f;
                #pragma unroll 4
                for (int j = 0; j < c; j++) off += g_csum[j * D + d];
                const float* src = g_fp + (size_t)c * 128 * D + d;
                float* dst = g_pref + (size_t)c * 128 * D + d;
                float run = off;
                #pragma unroll 4
                for (int r = 0; r < 128; r++) {
                    dst[(size_t)r * D] = run;
                    run += src[(size_t)r * D];
                }
                if (c == 63) g_pref[(size_t)N * D + d] = run;
            }
        }
    }

    // ===================== phase G: GEMM (denominator) =====================
    const int t0 = cum_tiles(bid);
    const int t1 = cum_tiles(bid + 1);

    if (t0 < t1) {
        const int wm = wid & 3, wn = wid >> 2;
        const int quad = lane >> 2, qt = lane & 3;
        const int rowA = wm * 32 + (lane & 15);
        const int hiA = lane >> 4, r7A = rowA & 7;
        const uint32_t aRowOff = (uint32_t)(rowA * 256);
        const int g = lane >> 3, r8 = lane & 7;
        const int nrowb = wn * 32 + ((g >> 1) << 3) + r8;
        const int segbLo = g & 1;
        const uint32_t bBase = sb + SM_RES + (uint32_t)(nrowb * 256);

        int tj = 0, rem = t0;
        while (rem >= tj + 1) { rem -= tj + 1; tj++; }
        int ti = rem;

        cp_tile(sb + SM_RES, tj * 128, tid);
        cp_tile(sb + SM_STR + (t0 & 1) * 32768, ti * 128, tid);
        CP_COMMIT();
        CP_WAIT0();
        __syncthreads();

        float cdn[8];
        #pragma unroll
        for (int p = 0; p < 8; p++) cdn[p] = 0.0f;

        for (int t = t0; t < t1; t++) {
            const int s = t & 1;
            const bool have_next = (t + 1) < t1;
            int nti = ti + 1, ntj = tj;
            if (nti > tj) { ntj = tj + 1; nti = 0; }
            const bool strip_change = have_next && (ntj != tj);

            if (have_next) {
                cp_tile(sb + SM_STR + ((t + 1) & 1) * 32768, nti * 128, tid);
                CP_COMMIT();
            }

            float acc[2][4][4];
            #pragma unroll
            for (int mi = 0; mi < 2; mi++)
                #pragma unroll
                for (int ni = 0; ni < 4; ni++)
                    #pragma unroll
                    for (int r = 0; r < 4; r++) acc[mi][ni][r] = 0.0f;

            const uint32_t aBase = sb + SM_STR + s * 32768 + aRowOff;
            #pragma unroll
            for (int k = 0; k < 8; k++) {
                uint32_t a[2][4];
                #pragma unroll
                for (int mi = 0; mi < 2; mi++) {
                    uint32_t addr = aBase + mi * 4096 + ((((k * 2 + hiA) ^ r7A)) << 4);
                    LDSM_X4(a[mi][0], a[mi][1], a[mi][2], a[mi][3], addr);
                }
                uint32_t b[4][2];
                #pragma unroll
                for (int p = 0; p < 2; p++) {
                    uint32_t addr = bBase + p * 4096 + ((((k * 2 + segbLo) ^ r8)) << 4);
                    LDSM_X4(b[2 * p][0], b[2 * p][1], b[2 * p + 1][0], b[2 * p + 1][1], addr);
                }
                #pragma unroll
                for (int mi = 0; mi < 2; mi++)
                    #pragma unroll
                    for (int ni = 0; ni < 4; ni++)
                        MMA16816(acc[mi][ni], a[mi], b[ni]);
            }

            float dn[4] = {0.0f, 0.0f, 0.0f, 0.0f};
            if (ti == tj) {
                #pragma unroll
                for (int mi = 0; mi < 2; mi++)
                    #pragma unroll
                    for (int rh = 0; rh < 2; rh++) {
                        const int slot = mi * 2 + rh;
                        const int selfnl = wm * 32 + mi * 16 + quad + rh * 8;
                        #pragma unroll
                        for (int p = 0; p < 8; p++) {
                            const int ni = p >> 1, c = p & 1;
                            const int nl = wn * 32 + ni * 8 + qt * 2 + c;
                            float e = ex2(acc[mi][ni][rh * 2 + c]);
                            dn[slot] += (nl == selfnl) ? 0.0f : e;
                        }
                    }
            } else {
                #pragma unroll
                for (int p = 0; p < 8; p++) {
                    const int ni = p >> 1, c = p & 1;
                    float a0 = 0.0f;
                    #pragma unroll
                    for (int mi = 0; mi < 2; mi++)
                        #pragma unroll
                        for (int rh = 0; rh < 2; rh++) {
                            float e = ex2(acc[mi][ni][rh * 2 + c]);
                            dn[mi * 2 + rh] += e;
                            a0 += e;
                        }
                    cdn[p] += a0;
                }
            }

            #pragma unroll
            for (int s2 = 0; s2 < 4; s2++) {
                float a = dn[s2];
                a += __shfl_xor_sync(0xffffffffu, a, 1);
                a += __shfl_xor_sync(0xffffffffu, a, 2);
                if (qt == 0) {
                    int gim = ti * 128 + wm * 32 + (s2 >> 1) * 16 + quad + (s2 & 1) * 8;
                    atomicAdd(&g_den[gim], a);
                }
            }

            if (strip_change || !have_next) {
                #pragma unroll
                for (int p = 0; p < 8; p++) {
                    float a = cdn[p];
                    #pragma unroll
                    for (int off = 4; off <= 16; off <<= 1)
                        a += __shfl_xor_sync(0xffffffffu, a, off);
                    if (quad == 0) {
                        int gj = tj * 128 + wn * 32 + (p >> 1) * 8 + qt * 2 + (p & 1);
                        atomicAdd(&g_den[gj], a);
                    }
                    cdn[p] = 0.0f;
                }
            }

            CP_WAIT0();
            __syncthreads();
            if (strip_change) {
                cp_tile(sb + SM_RES, ntj * 128, tid);
                CP_COMMIT();
                CP_WAIT0();
                __syncthreads();
            }
            ti = nti; tj = ntj;
        }
    }

    // ===================== grid barrier =====================
    __threadfence();
    __syncthreads();
    if (tid == 0) {
        atomicAdd(&g_cnt_gemm, 1u);
        while (ld_acq(&g_cnt_gemm) < (unsigned)NCTA) __nanosleep(128);
    }
    __syncthreads();

    // ===================== phase F: final loss =====================
    {
        float* sslab = (float*)smem;          // 32 KB (GEMM buffers dead now)
        for (int k = tid; k < N; k += NTHR) sslab[k] = g_slab[k];
        __syncthreads();

        float wsum = 0.0f;
        #pragma unroll 1
        for (int k = bid * 16 + wid; k < N; k += NCTA * 16) {
            float li = sslab[k];
            int l = 0, r = N;
            while (l < r) { int m = (l + r) >> 1; if (li - sslab[m] < THRESH) r = m; else l = m + 1; }
            const int lo = l;
            l = 0; r = N;
            while (l < r) { int m = (l + r) >> 1; if (sslab[m] - li < THRESH) l = m + 1; else r = m; }
            const int hi = l;

            float dot = 0.0f;
            const float* fk = g_fp + (size_t)k * D;
            const float* Ph = g_pref + (size_t)hi * D;
            const float* Pl = g_pref + (size_t)lo * D;
            #pragma unroll
            for (int qd = 0; qd < 4; qd++) {
                int d = lane + qd * 32;
                dot += fk[d] * (Ph[d] - Pl[d]);
            }
            #pragma unroll
            for (int off = 16; off; off >>= 1)
                dot += __shfl_xor_sync(0xffffffffu, dot, off);

            if (lane == 0) {
                int i = g_sidx[k];
                float pcv = (float)(hi - lo - 1);
                wsum += (dot - 1.0f) * INV_T / pcv - LN2 * log2f(g_den[i]);
            }
        }
        if (lane == 0) atomicAdd(&g_loss, wsum);

        __threadfence();
        __syncthreads();
        if (tid == 0) {
            unsigned tk = atomicAdd(&g_cnt_out, 1u);
            if (tk == (unsigned)(NCTA - 1))
                out[0] = -(atomicAdd(&g_loss, 0.0f)) / (float)N;
        }
    }
}

// ---------------------------------------------------------------------------
extern "C" void kernel_launch(void* const* d_in, const int* in_sizes, int n_in,
                              void* d_out, int out_size) {
    const float* features = (const float*)d_in[0];
    const float* labels   = (const float*)d_in[1];
    float* out = (float*)d_out;

    cudaFuncSetAttribute(main_kernel, cudaFuncAttributeMaxDynamicSharedMemorySize, SM_TOTAL);

    prep_kernel<<<N / 8, 256>>>(features);
    main_kernel<<<NCTA, NTHR, SM_TOTAL>>>(labels, out);
}

// round 10
// speedup vs baseline: 2.5627x; 1.4146x over previous
#include <cuda_runtime.h>
#include <cuda_bf16.h>
#include <cstdint>
#include <math.h>

#define N 8192
#define D 128
#define NCTA 148
#define NTT 2080               /* upper-triangle tiles: 64*65/2 */
#define NTHR 512
#define NBUCK 4096
#define INV_T 14.2857142857142857f
#define LN2 0.69314718055994531f
#define SQRT_C 4.5398160486f   /* sqrt((1/0.07)*log2(e)) */
#define THRESH 0.1f

// Scratch (no cudaMalloc allowed)
__device__ __nv_bfloat16 g_fbf[N * D];       // normalized * SQRT_C, bf16
__device__ float g_fn[N * D];                // normalized, fp32
__device__ float g_fp[N * D];                // normalized, sorted order
__device__ float g_pref[(N + 1) * D];        // exclusive prefix sums (sorted)
__device__ float g_csum[64 * D];             // per-chunk sums
__device__ float g_slab[N];                  // sorted labels
__device__ int   g_sidx[N];                  // sorted -> original index
__device__ float g_den[N];
__device__ float g_loss;
__device__ unsigned g_cnt_gemm, g_cnt_out;

// ---- main kernel SMEM layout (bytes) ----
#define SM_RES   0          /* resident 128-row j-strip, 32 KB, XOR-swizzled */
#define SM_STR   32768      /* 2 x 32 KB double-buffered streaming A tiles */
#define SM_TOTAL 98304

__device__ __forceinline__ uint32_t smem_u32(const void* p) {
    uint32_t a;
    asm("{ .reg .u64 t; cvta.to.shared.u64 t, %1; cvt.u32.u64 %0, t; }" : "=r"(a) : "l"(p));
    return a;
}
__device__ __forceinline__ float ex2(float x) {
    float r;
    asm("ex2.approx.ftz.f32 %0, %1;" : "=f"(r) : "f"(x));
    return r;
}
__device__ __forceinline__ unsigned ld_acq(unsigned* p) {
    unsigned v;
    asm volatile("ld.acquire.gpu.u32 %0, [%1];" : "=r"(v) : "l"(p) : "memory");
    return v;
}

#define LDSM_X4(r0, r1, r2, r3, addr) \
    asm volatile("ldmatrix.sync.aligned.m8n8.x4.shared.b16 {%0,%1,%2,%3}, [%4];" \
                 : "=r"(r0), "=r"(r1), "=r"(r2), "=r"(r3) : "r"(addr))

#define MMA16816(d, a, b) \
    asm volatile("mma.sync.aligned.m16n8k16.row.col.f32.bf16.bf16.f32 " \
                 "{%0,%1,%2,%3}, {%4,%5,%6,%7}, {%8,%9}, {%0,%1,%2,%3};" \
                 : "+f"((d)[0]), "+f"((d)[1]), "+f"((d)[2]), "+f"((d)[3]) \
                 : "r"((a)[0]), "r"((a)[1]), "r"((a)[2]), "r"((a)[3]), \
                   "r"((b)[0]), "r"((b)[1]))

#define CP_ASYNC16(dst, src) \
    asm volatile("cp.async.cg.shared.global [%0], [%1], 16;" \
                 :: "r"(dst), "l"(src) : "memory")
#define CP_COMMIT() asm volatile("cp.async.commit_group;" ::: "memory")
#define CP_WAIT0()  asm volatile("cp.async.wait_group 0;" ::: "memory")

__device__ __forceinline__ uint32_t swz(int row, int seg) {
    return (uint32_t)(row * 256 + ((seg ^ (row & 7)) << 4));
}

__device__ __forceinline__ void cp_tile(uint32_t dst_base, int rowBase, int tid) {
    size_t gsrc = __cvta_generic_to_global(g_fbf) + (size_t)rowBase * 256;
    #pragma unroll
    for (int it = 0; it < 4; it++) {
        int u = it * NTHR + tid;         // 2048 16B units
        int row = u >> 4, seg = u & 15;
        CP_ASYNC16(dst_base + swz(row, seg), (const void*)(gsrc + (size_t)u * 16));
    }
}

// ---------------------------------------------------------------------------
// Kernel 1: normalize rows (clamp at 1e-8); fp32 + bf16*SQRT_C copies; zero state
// ---------------------------------------------------------------------------
__global__ void prep_kernel(const float* __restrict__ features) {
    int warp = threadIdx.x >> 5, lane = threadIdx.x & 31;
    int row = blockIdx.x * 8 + warp;

    float4 v = ((const float4*)(features + row * D))[lane];
    float ss = v.x * v.x + v.y * v.y + v.z * v.z + v.w * v.w;
    #pragma unroll
    for (int off = 16; off; off >>= 1) ss += __shfl_xor_sync(0xffffffffu, ss, off);
    float sc = 1.0f / fmaxf(sqrtf(ss), 1e-8f);

    float4 nv;
    nv.x = v.x * sc; nv.y = v.y * sc; nv.z = v.z * sc; nv.w = v.w * sc;
    ((float4*)(g_fn + (size_t)row * D))[lane] = nv;

    __nv_bfloat162 p0 = __floats2bfloat162_rn(nv.x * SQRT_C, nv.y * SQRT_C);
    __nv_bfloat162 p1 = __floats2bfloat162_rn(nv.z * SQRT_C, nv.w * SQRT_C);
    uint2 st;
    st.x = *(const uint32_t*)&p0;
    st.y = *(const uint32_t*)&p1;
    ((uint2*)(g_fbf + (size_t)row * D))[lane] = st;

    int gt = blockIdx.x * blockDim.x + threadIdx.x;
    if (gt < N) g_den[gt] = 0.0f;
    if (gt == 0) { g_loss = 0.0f; g_cnt_gemm = 0u; g_cnt_out = 0u; }
}

// ---------------------------------------------------------------------------
// Kernel 2: bucket sort of (label, idx). One CTA, 1024 threads, 96KB smem.
// ---------------------------------------------------------------------------
__global__ void sort_kernel(const float* __restrict__ labels) {
    extern __shared__ char smem[];
    unsigned long long* keys = (unsigned long long*)smem;       // 64 KB
    unsigned* cnt = (unsigned*)(smem + 65536);                  // 16 KB
    unsigned* bst = (unsigned*)(smem + 65536 + 16384);          // 16 KB
    __shared__ unsigned wtot[33];

    const int tid = threadIdx.x;
    const int wid = tid >> 5, lane = tid & 31;

    for (int b = tid; b < NBUCK; b += 1024) cnt[b] = 0u;
    __syncthreads();
    #pragma unroll
    for (int it = 0; it < 8; it++) {
        float lv = labels[it * 1024 + tid];
        int b = max(0, min(NBUCK - 1, (int)(lv * (float)NBUCK)));
        atomicAdd(&cnt[b], 1u);
    }
    __syncthreads();
    // exclusive scan of 4096 counts: 4 per thread + warp scan + warp totals
    unsigned loc[4]; unsigned s = 0u;
    #pragma unroll
    for (int j = 0; j < 4; j++) { loc[j] = s; s += cnt[tid * 4 + j]; }
    unsigned incl = s;
    #pragma unroll
    for (int off = 1; off < 32; off <<= 1) {
        unsigned v = __shfl_up_sync(0xffffffffu, incl, off);
        if (lane >= off) incl += v;
    }
    if (lane == 31) wtot[wid + 1] = incl;
    if (tid == 0) wtot[0] = 0u;
    __syncthreads();
    if (tid == 0)
        for (int w = 1; w <= 32; w++) wtot[w] += wtot[w - 1];
    __syncthreads();
    unsigned base = wtot[wid] + incl - s;
    #pragma unroll
    for (int j = 0; j < 4; j++) bst[tid * 4 + j] = base + loc[j];
    __syncthreads();
    // scatter (bst becomes bucket END after this)
    #pragma unroll
    for (int it = 0; it < 8; it++) {
        int k = it * 1024 + tid;
        float lv = labels[k];
        int b = max(0, min(NBUCK - 1, (int)(lv * (float)NBUCK)));
        unsigned pos = atomicAdd(&bst[b], 1u);
        keys[pos] = ((unsigned long long)__float_as_uint(lv) << 32) | (unsigned)k;
    }
    __syncthreads();
    // per-bucket insertion sort (mean occupancy = 2)
    #pragma unroll 1
    for (int b = tid; b < NBUCK; b += 1024) {
        unsigned st = (b == 0) ? 0u : bst[b - 1];
        unsigned n = cnt[b];
        for (unsigned x = st + 1; x < st + n; x++) {
            unsigned long long v = keys[x];
            unsigned y = x;
            while (y > st && keys[y - 1] > v) { keys[y] = keys[y - 1]; y--; }
            keys[y] = v;
        }
    }
    __syncthreads();
    for (int k = tid; k < N; k += 1024) {
        unsigned long long v = keys[k];
        g_slab[k] = __uint_as_float((unsigned)(v >> 32));
        g_sidx[k] = (int)(v & 0xffffffffu);
    }
}

// ---------------------------------------------------------------------------
// Kernel 3: permute features into sorted order (via smem staging) + chunk sums.
// 64 CTAs x 256 threads; CTA c handles sorted rows [c*128, c*128+128).
// ---------------------------------------------------------------------------
__global__ void perm_kernel() {
    extern __shared__ char smem[];
    float* sData = (float*)smem;                 // 64 KB: 128 rows x 128 f32
    int* sIdx = (int*)(smem + 65536);            // 512 B
    const int tid = threadIdx.x;
    const int c = blockIdx.x;

    if (tid < 128) sIdx[tid] = g_sidx[c * 128 + tid];
    __syncthreads();

    // gather 128 rows (independent addresses -> deep MLP)
    #pragma unroll
    for (int it = 0; it < 16; it++) {
        int u = it * 256 + tid;                  // 4096 float4 units
        int row = u >> 5, seg = u & 31;
        ((float4*)sData)[u] = ((const float4*)(g_fn + (size_t)sIdx[row] * D))[seg];
    }
    __syncthreads();

    // write coalesced + per-column chunk sums
    float4* dst = (float4*)(g_fp + (size_t)c * 128 * D);
    #pragma unroll
    for (int it = 0; it < 16; it++) {
        int u = it * 256 + tid;
        dst[u] = ((const float4*)sData)[u];
    }
    if (tid < 128) {
        float s = 0.0f;
        #pragma unroll 16
        for (int r = 0; r < 128; r++) s += sData[r * D + tid];
        g_csum[c * D + tid] = s;
    }
}

// ---------------------------------------------------------------------------
// Kernel 4: exclusive prefix sums P[k][d], k in [c*128, c*128+128). 64 CTAs x 128.
// ---------------------------------------------------------------------------
__global__ void scan2_kernel() {
    const int d = threadIdx.x;          // 128 threads = columns
    const int c = blockIdx.x;
    float off = 0.0f;
    #pragma unroll 8
    for (int j = 0; j < c; j++) off += g_csum[j * D + d];
    const float* src = g_fp + (size_t)c * 128 * D + d;
    float* dst = g_pref + (size_t)c * 128 * D + d;
    float run = off;
    #pragma unroll 8
    for (int r = 0; r < 128; r++) {
        dst[(size_t)r * D] = run;
        run += src[(size_t)r * D];
    }
    if (c == 63) g_pref[(size_t)N * D + d] = run;
}

// ---------------------------------------------------------------------------
// Kernel 5: persistent fused HMMA GEMM over the upper triangle (denominator
// only), then grid barrier, then final loss (smem binary searches + prefix
// dots). 148 CTAs x 512 threads.
// ---------------------------------------------------------------------------
__global__ void __launch_bounds__(NTHR, 1)
main_kernel(float* __restrict__ out) {
    extern __shared__ char smem[];
    const uint32_t sb = smem_u32(smem);
    const int tid  = threadIdx.x;
    const int wid  = tid >> 5;
    const int lane = tid & 31;
    const int bid  = (int)blockIdx.x;
    const int wm = wid & 3;          // 0..3 -> m-block of 32
    const int wn = wid >> 2;         // 0..3 -> n-block of 32
    const int quad = lane >> 2;
    const int qt   = lane & 3;

    // --- ldmatrix per-lane bases ---
    const int rowA = wm * 32 + (lane & 15);
    const int hiA  = lane >> 4;
    const int r7A  = rowA & 7;
    const uint32_t aRowOff = (uint32_t)(rowA * 256);
    const int g   = lane >> 3;
    const int r8  = lane & 7;
    const int nrowb = wn * 32 + ((g >> 1) << 3) + r8;
    const int segbLo = g & 1;
    const uint32_t bBase = sb + SM_RES + (uint32_t)(nrowb * 256);

    const int t0 = ((int)bid * NTT) / NCTA;
    const int t1 = (((int)bid + 1) * NTT) / NCTA;

    // map t0 -> (tj, ti): column-major triangle, strip tj has tj+1 tiles
    int tj = 0, rem = t0;
    while (rem >= tj + 1) { rem -= tj + 1; tj++; }
    int ti = rem;

    cp_tile(sb + SM_RES, tj * 128, tid);
    cp_tile(sb + SM_STR + (t0 & 1) * 32768, ti * 128, tid);
    CP_COMMIT();
    CP_WAIT0();
    __syncthreads();

    float cdn[8];
    #pragma unroll
    for (int p = 0; p < 8; p++) cdn[p] = 0.0f;

    for (int t = t0; t < t1; t++) {
        const int s = t & 1;
        const bool have_next = (t + 1) < t1;
        int nti = ti + 1, ntj = tj;
        if (nti > tj) { ntj = tj + 1; nti = 0; }
        const bool strip_change = have_next && (ntj != tj);

        if (have_next) {
            cp_tile(sb + SM_STR + ((t + 1) & 1) * 32768, nti * 128, tid);
            CP_COMMIT();
        }

        // ---- mainloop: 128x128 tile, K=128 ----
        float acc[2][4][4];
        #pragma unroll
        for (int mi = 0; mi < 2; mi++)
            #pragma unroll
            for (int ni = 0; ni < 4; ni++)
                #pragma unroll
                for (int r = 0; r < 4; r++) acc[mi][ni][r] = 0.0f;

        const uint32_t aBase = sb + SM_STR + s * 32768 + aRowOff;
        #pragma unroll
        for (int k = 0; k < 8; k++) {
            uint32_t a[2][4];
            #pragma unroll
            for (int mi = 0; mi < 2; mi++) {
                uint32_t addr = aBase + mi * 4096 + ((((k * 2 + hiA) ^ r7A)) << 4);
                LDSM_X4(a[mi][0], a[mi][1], a[mi][2], a[mi][3], addr);
            }
            uint32_t b[4][2];
            #pragma unroll
            for (int p = 0; p < 2; p++) {
                uint32_t addr = bBase + p * 4096 + ((((k * 2 + segbLo) ^ r8)) << 4);
                LDSM_X4(b[2 * p][0], b[2 * p][1], b[2 * p + 1][0], b[2 * p + 1][1], addr);
            }
            #pragma unroll
            for (int mi = 0; mi < 2; mi++)
                #pragma unroll
                for (int ni = 0; ni < 4; ni++)
                    MMA16816(acc[mi][ni], a[mi], b[ni]);
        }

        // ---- epilogue: denominator only (acc is already the ex2 argument) ----
        float dn[4] = {0.0f, 0.0f, 0.0f, 0.0f};
        if (ti == tj) {
            #pragma unroll
            for (int mi = 0; mi < 2; mi++)
                #pragma unroll
                for (int rh = 0; rh < 2; rh++) {
                    const int slot = mi * 2 + rh;
                    const int selfnl = wm * 32 + mi * 16 + quad + rh * 8;
                    #pragma unroll
                    for (int p = 0; p < 8; p++) {
                        const int ni = p >> 1, c = p & 1;
                        const int nl = wn * 32 + ni * 8 + qt * 2 + c;
                        float e = ex2(acc[mi][ni][rh * 2 + c]);
                        dn[slot] += (nl == selfnl) ? 0.0f : e;
                    }
                }
        } else {
            #pragma unroll
            for (int p = 0; p < 8; p++) {
                const int ni = p >> 1, c = p & 1;
                float a0 = 0.0f;
                #pragma unroll
                for (int mi = 0; mi < 2; mi++)
                    #pragma unroll
                    for (int rh = 0; rh < 2; rh++) {
                        float e = ex2(acc[mi][ni][rh * 2 + c]);
                        dn[mi * 2 + rh] += e;
                        a0 += e;
                    }
                cdn[p] += a0;
            }
        }

        // ---- row flush (2-round qt shuffle) ----
        #pragma unroll
        for (int s2 = 0; s2 < 4; s2++) {
            float a = dn[s2];
            a += __shfl_xor_sync(0xffffffffu, a, 1);
            a += __shfl_xor_sync(0xffffffffu, a, 2);
            if (qt == 0) {
                int gim = ti * 128 + wm * 32 + (s2 >> 1) * 16 + quad + (s2 & 1) * 8;
                atomicAdd(&g_den[gim], a);
            }
        }

        // ---- column flush at strip end / range end ----
        if (strip_change || !have_next) {
            #pragma unroll
            for (int p = 0; p < 8; p++) {
                float a = cdn[p];
                #pragma unroll
                for (int off = 4; off <= 16; off <<= 1)
                    a += __shfl_xor_sync(0xffffffffu, a, off);
                if (quad == 0) {
                    int gj = tj * 128 + wn * 32 + (p >> 1) * 8 + qt * 2 + (p & 1);
                    atomicAdd(&g_den[gj], a);
                }
                cdn[p] = 0.0f;
            }
        }

        CP_WAIT0();
        __syncthreads();
        if (strip_change) {
            cp_tile(sb + SM_RES, ntj * 128, tid);
            CP_COMMIT();
            CP_WAIT0();
            __syncthreads();
        }
        ti = nti; tj = ntj;
    }

    // ===================== grid barrier =====================
    __threadfence();
    __syncthreads();
    if (tid == 0) {
        atomicAdd(&g_cnt_gemm, 1u);
        while (ld_acq(&g_cnt_gemm) < (unsigned)NCTA) __nanosleep(128);
    }
    __syncthreads();

    // ===================== final loss =====================
    {
        float* sslab = (float*)smem;          // 32 KB (GEMM buffers dead now)
        for (int k = tid; k < N; k += NTHR) sslab[k] = g_slab[k];
        __syncthreads();

        float wsum = 0.0f;
        #pragma unroll 1
        for (int k = bid * 16 + wid; k < N; k += NCTA * 16) {
            float li = sslab[k];
            int l = 0, r = N;
            while (l < r) { int m = (l + r) >> 1; if (li - sslab[m] < THRESH) r = m; else l = m + 1; }
            const int lo = l;
            l = 0; r = N;
            while (l < r) { int m = (l + r) >> 1; if (sslab[m] - li < THRESH) l = m + 1; else r = m; }
            const int hi = l;

            float dot = 0.0f;
            const float* fk = g_fp + (size_t)k * D;
            const float* Ph = g_pref + (size_t)hi * D;
            const float* Pl = g_pref + (size_t)lo * D;
            #pragma unroll
            for (int qd = 0; qd < 4; qd++) {
                int d = lane + qd * 32;
                dot += fk[d] * (Ph[d] - Pl[d]);
            }
            #pragma unroll
            for (int off = 16; off; off >>= 1)
                dot += __shfl_xor_sync(0xffffffffu, dot, off);

            if (lane == 0) {
                int i = g_sidx[k];
                float pcv = (float)(hi - lo - 1);
                wsum += (dot - 1.0f) * INV_T / pcv - LN2 * log2f(g_den[i]);
            }
        }
        if (lane == 0) atomicAdd(&g_loss, wsum);

        __threadfence();
        __syncthreads();
        if (tid == 0) {
            unsigned tk = atomicAdd(&g_cnt_out, 1u);
            if (tk == (unsigned)(NCTA - 1))
                out[0] = -(atomicAdd(&g_loss, 0.0f)) / (float)N;
        }
    }
}

// ---------------------------------------------------------------------------
extern "C" void kernel_launch(void* const* d_in, const int* in_sizes, int n_in,
                              void* d_out, int out_size) {
    const float* features = (const float*)d_in[0];
    const float* labels   = (const float*)d_in[1];
    float* out = (float*)d_out;

    cudaFuncSetAttribute(main_kernel, cudaFuncAttributeMaxDynamicSharedMemorySize, SM_TOTAL);
    cudaFuncSetAttribute(sort_kernel, cudaFuncAttributeMaxDynamicSharedMemorySize, 98304);
    cudaFuncSetAttribute(perm_kernel, cudaFuncAttributeMaxDynamicSharedMemorySize, 66048);

    prep_kernel<<<N / 8, 256>>>(features);
    sort_kernel<<<1, 1024, 98304>>>(labels);
    perm_kernel<<<64, 256, 66048>>>();
    scan2_kernel<<<64, 128>>>();
    main_kernel<<<NCTA, NTHR, SM_TOTAL>>>(out);
}